// round 9
// baseline (speedup 1.0000x reference)
#include <cuda_runtime.h>
#include <cuda_bf16.h>
#include <cstdint>

// Problem dims
#define MDIM 256
#define TDIM 512
#define NXDIM 256
#define UDIM 256

// Scratch for x-projections: 3 matrices x [T][M][U] fp32 = 402 MB.
#define XP_STRIDE (33554432ULL) // 512*256*256
__device__ float g_xp[3ULL * XP_STRIDE];

// ---------------- packed f32x2 helpers ----------------
#define FFMA2(c_, a_, b_) \
    asm volatile("fma.rn.f32x2 %0, %1, %2, %0;" : "+l"(c_) : "l"(a_), "l"(b_))

__device__ __forceinline__ unsigned long long dup2(float a) {
    unsigned long long r;
    asm("mov.b64 %0, {%1, %1};" : "=l"(r) : "f"(a));
    return r;
}
__device__ __forceinline__ void unpack2(float& lo, float& hi, unsigned long long v) {
    asm("mov.b64 {%0, %1}, %2;" : "=f"(lo), "=f"(hi) : "l"(v));
}
__device__ __forceinline__ float hsum2(unsigned long long v) {
    float lo, hi; unpack2(lo, hi, v); return lo + hi;
}

// ---------------- cluster / DSMEM helpers ----------------
__device__ __forceinline__ uint32_t smem_u32(const void* p) {
    uint32_t a;
    asm("{ .reg .u64 t; cvta.to.shared.u64 t, %1; cvt.u32.u64 %0, t; }"
        : "=r"(a) : "l"(p));
    return a;
}
__device__ __forceinline__ uint32_t mapa_rank(uint32_t addr, uint32_t rank) {
    uint32_t r;
    asm("mapa.shared::cluster.u32 %0, %1, %2;" : "=r"(r) : "r"(addr), "r"(rank));
    return r;
}
__device__ __forceinline__ void st_cluster_f32(uint32_t addr, float v) {
    asm volatile("st.shared::cluster.f32 [%0], %1;" :: "r"(addr), "f"(v) : "memory");
}
__device__ __forceinline__ uint32_t ctarank() {
    uint32_t r; asm("mov.u32 %0, %%cluster_ctarank;" : "=r"(r)); return r;
}
#define CLUSTER_SYNC_() do { \
    asm volatile("barrier.cluster.arrive.aligned;" ::: "memory"); \
    asm volatile("barrier.cluster.wait.aligned;" ::: "memory"); } while (0)

// mbarrier: init (count arrivals), remote release-arrive, local acquire-wait
__device__ __forceinline__ void mbar_init(uint32_t bar, uint32_t cnt) {
    asm volatile("mbarrier.init.shared.b64 [%0], %1;" :: "r"(bar), "r"(cnt) : "memory");
}
__device__ __forceinline__ void mbar_arrive_rank(uint32_t local_bar, uint32_t rank) {
    uint32_t remote = mapa_rank(local_bar, rank);
    asm volatile("mbarrier.arrive.release.cluster.shared::cluster.b64 _, [%0];"
                 :: "r"(remote) : "memory");
}
__device__ __forceinline__ void mbar_wait_parity(uint32_t bar, uint32_t parity) {
    uint32_t done;
    asm volatile(
        "{\n\t.reg .pred p;\n\t"
        "mbarrier.try_wait.parity.acquire.cluster.shared::cta.b64 p, [%1], %2;\n\t"
        "selp.b32 %0, 1, 0, p;\n\t}"
        : "=r"(done) : "r"(bar), "r"(parity) : "memory");
    if (!done) {
        asm volatile(
            "{\n\t.reg .pred P1;\n\t"
            "WLOOP_%=:\n\t"
            "mbarrier.try_wait.parity.acquire.cluster.shared::cta.b64 P1, [%0], %1, 0x989680;\n\t"
            "@P1 bra.uni WDONE_%=;\n\t"
            "bra.uni WLOOP_%=;\n\t"
            "WDONE_%=:\n\t}"
            :: "r"(bar), "r"(parity) : "memory");
    }
}

// =====================================================================
// Phase 1: x projections (unchanged — ~1.06 ms, ~72% of fp32x2 peak).
// =====================================================================
__global__ __launch_bounds__(256, 1)
void xproj_kernel(const float* __restrict__ x,
                  const float* __restrict__ w_u,
                  const float* __restrict__ w_r,
                  const float* __restrict__ w_c)
{
    const float* __restrict__ w =
        (blockIdx.z == 0) ? w_u : ((blockIdx.z == 1) ? w_r : w_c);
    float* __restrict__ outp = g_xp + (size_t)blockIdx.z * XP_STRIDE;

    const int tid = threadIdx.x;
    const int g0  = blockIdx.x * 128;
    const int t   = g0 >> 8;
    const int m0  = g0 & 255;
    const int n0  = blockIdx.y * 128;

    __shared__ float As[16][132];
    __shared__ float Bs[16][128];

    const int tx = tid & 15;
    const int ty = tid >> 4;

    unsigned long long acc[8][4];
    #pragma unroll
    for (int i = 0; i < 8; i++)
        #pragma unroll
        for (int j = 0; j < 4; j++) acc[i][j] = 0ULL;

    for (int kk = 0; kk < NXDIM; kk += 16) {
        #pragma unroll
        for (int l = 0; l < 2; l++) {
            int f  = tid + l * 256;
            int i  = f >> 2;
            int kv = (f & 3) * 4;
            const float4 v = *(const float4*)(x +
                ((size_t)(m0 + i) * TDIM + t) * NXDIM + kk + kv);
            As[kv + 0][i] = v.x;
            As[kv + 1][i] = v.y;
            As[kv + 2][i] = v.z;
            As[kv + 3][i] = v.w;
        }
        #pragma unroll
        for (int l = 0; l < 2; l++) {
            int f  = tid + l * 256;
            int k  = f >> 5;
            int nn = (f & 31) * 4;
            *(float4*)&Bs[k][nn] =
                *(const float4*)(w + (size_t)(kk + k) * UDIM + n0 + nn);
        }
        __syncthreads();

        #pragma unroll
        for (int k = 0; k < 16; k++) {
            float4 a0v = *(const float4*)&As[k][ty * 8];
            float4 a1v = *(const float4*)&As[k][ty * 8 + 4];
            const unsigned long long* bp =
                (const unsigned long long*)&Bs[k][tx * 8];
            unsigned long long b0 = bp[0], b1 = bp[1], b2 = bp[2], b3 = bp[3];
            float av[8] = {a0v.x, a0v.y, a0v.z, a0v.w,
                           a1v.x, a1v.y, a1v.z, a1v.w};
            #pragma unroll
            for (int i = 0; i < 8; i++) {
                unsigned long long ad = dup2(av[i]);
                FFMA2(acc[i][0], ad, b0);
                FFMA2(acc[i][1], ad, b1);
                FFMA2(acc[i][2], ad, b2);
                FFMA2(acc[i][3], ad, b3);
            }
        }
        __syncthreads();
    }

    #pragma unroll
    for (int i = 0; i < 8; i++) {
        int g = g0 + ty * 8 + i;
        float o[8];
        unpack2(o[0], o[1], acc[i][0]);
        unpack2(o[2], o[3], acc[i][1]);
        unpack2(o[4], o[5], acc[i][2]);
        unpack2(o[6], o[7], acc[i][3]);
        float* op = outp + (size_t)g * UDIM + n0 + tx * 8;
        *(float4*)(op)     = make_float4(o[0], o[1], o[2], o[3]);
        *(float4*)(op + 4) = make_float4(o[4], o[5], o[6], o[7]);
    }
}

// =====================================================================
// Phase 2: GRU scan — 32 clusters x 4 CTAs, 512 threads/CTA.
//   Thread = (n_l 0..63, rp 0..3, kh 0..1): 2 rows (rp, rp+4), half
//   the k range via 4-float interleave (k = i*8 + kh*4).  Stride 264
//   keeps every 8-lane LDS128 phase bank-conflict-free.
//   Per step: phase A (u,r gates) -> DSMEM bcast h -> mbar sync
//           -> phase B (candidate) -> DSMEM bcast c -> mbar sync.
// =====================================================================
#define WST 264
#define OFF_WU 16
#define OFF_WR (16 + 64 * WST)
#define OFF_WC (16 + 128 * WST)
#define OFF_C  (16 + 192 * WST)
#define OFF_H  (16 + 200 * WST)
#define SM_FLOATS (16 + 208 * WST)     // 54928 floats
#define SM_BYTES (SM_FLOATS * 4)       // 219712 bytes

__device__ __forceinline__ float sigmoid_f(float z) {
    return 1.0f / (1.0f + __expf(-z));
}

__global__ __launch_bounds__(512, 1) __cluster_dims__(4, 1, 1)
void gru_scan3(const float* __restrict__ wuc,
               const float* __restrict__ wrc,
               const float* __restrict__ wcc,
               const float* __restrict__ bu,
               const float* __restrict__ br,
               const float* __restrict__ bc,
               const float* __restrict__ a0,
               float* __restrict__ out)
{
    extern __shared__ float sm[];
    float* wu_s = sm + OFF_WU;
    float* wr_s = sm + OFF_WR;
    float* wc_s = sm + OFF_WC;
    float* c_s  = sm + OFF_C;
    float* h_s  = sm + OFF_H;

    const int tid = threadIdx.x;
    const uint32_t rank = ctarank();
    const int n0 = (int)rank * 64;
    const int r0 = (blockIdx.x >> 2) * 8;

    const int n_l = tid >> 3;
    const int rp  = (tid >> 1) & 3;
    const int kh  = tid & 1;
    const int ra  = rp, rb = rp + 4;
    const int n_g = n0 + n_l;
    const int kofs = kh * 4;

    const uint32_t barH = smem_u32(sm);       // 8 bytes
    const uint32_t barC = smem_u32(sm) + 8;   // 8 bytes

    if (tid == 0) { mbar_init(barH, 4); mbar_init(barC, 4); }

    // ---- load weight slices transposed: wT[n_l][k] = W[k][n0+n_l] ----
    for (int i = tid; i < 64 * 256; i += 512) {
        int k  = i >> 6;
        int nl = i & 63;
        wu_s[nl * WST + k] = wuc[k * UDIM + n0 + nl];
        wr_s[nl * WST + k] = wrc[k * UDIM + n0 + nl];
        wc_s[nl * WST + k] = wcc[k * UDIM + n0 + nl];
    }
    // ---- init c_s (8 rows) ----
    for (int i = tid; i < 8 * 256; i += 512) {
        int r = i >> 8, k = i & 255;
        c_s[r * WST + k] = a0[(size_t)(r0 + r) * UDIM + k];
    }
    float c_a = a0[(size_t)(r0 + ra) * UDIM + n_g];
    float c_b = a0[(size_t)(r0 + rb) * UDIM + n_g];
    const float bun = bu[n_g], brn = br[n_g], bcn = bc[n_g];

    // ---- DSMEM broadcast targets: this thread publishes ONE value
    //      (kh==0 -> row ra, kh==1 -> row rb) to all 4 ranks ----
    const int myrow = kh ? rb : ra;
    uint32_t h_loc = smem_u32(&h_s[myrow * WST + n_g]);
    uint32_t c_loc = smem_u32(&c_s[myrow * WST + n_g]);
    uint32_t h_dst[4], c_dst[4];
    #pragma unroll
    for (int d = 0; d < 4; d++) {
        h_dst[d] = mapa_rank(h_loc, d);
        c_dst[d] = mapa_rank(c_loc, d);
    }

    __syncthreads();
    CLUSTER_SYNC_();   // mbarrier inits + weight/c tiles visible cluster-wide

    const float* __restrict__ xu = g_xp;
    const float* __restrict__ xr = g_xp + XP_STRIDE;
    const float* __restrict__ xc = g_xp + 2ULL * XP_STRIDE;

    const float* wup = wu_s + n_l * WST + kofs;
    const float* wrp = wr_s + n_l * WST + kofs;
    const float* wcp = wc_s + n_l * WST + kofs;
    const float* cap = c_s + ra * WST + kofs;
    const float* cbp = c_s + rb * WST + kofs;
    const float* hap = h_s + ra * WST + kofs;
    const float* hbp = h_s + rb * WST + kofs;

    for (int t = 0; t < TDIM; t++) {
        const uint32_t ph = (uint32_t)(t & 1);

        // prefetch x-projection terms (hidden under phase A)
        const size_t xb = ((size_t)t * MDIM + r0) * UDIM + n_g;
        const float xu_a = __ldg(xu + xb + (size_t)ra * UDIM);
        const float xu_b = __ldg(xu + xb + (size_t)rb * UDIM);
        const float xr_a = __ldg(xr + xb + (size_t)ra * UDIM);
        const float xr_b = __ldg(xr + xb + (size_t)rb * UDIM);
        const float xc_a = __ldg(xc + xb + (size_t)ra * UDIM);
        const float xc_b = __ldg(xc + xb + (size_t)rb * UDIM);

        // ---- phase A: pre_u, pre_r (this thread's k-half) ----
        unsigned long long aUa0 = 0, aUa1 = 0, aUb0 = 0, aUb1 = 0;
        unsigned long long aRa0 = 0, aRa1 = 0, aRb0 = 0, aRb1 = 0;
        #pragma unroll 8
        for (int i = 0; i < 32; i++) {
            const int o = i * 8;   // floats; k = i*8 + kh*4 via kofs
            ulonglong2 wu = *(const ulonglong2*)(wup + o);
            ulonglong2 wr = *(const ulonglong2*)(wrp + o);
            ulonglong2 ca = *(const ulonglong2*)(cap + o);
            ulonglong2 cb = *(const ulonglong2*)(cbp + o);
            FFMA2(aUa0, ca.x, wu.x); FFMA2(aUa1, ca.y, wu.y);
            FFMA2(aUb0, cb.x, wu.x); FFMA2(aUb1, cb.y, wu.y);
            FFMA2(aRa0, ca.x, wr.x); FFMA2(aRa1, ca.y, wr.y);
            FFMA2(aRb0, cb.x, wr.x); FFMA2(aRb1, cb.y, wr.y);
        }
        float pua = hsum2(aUa0) + hsum2(aUa1);
        float pub = hsum2(aUb0) + hsum2(aUb1);
        float pra = hsum2(aRa0) + hsum2(aRa1);
        float prb = hsum2(aRb0) + hsum2(aRb1);
        pua += __shfl_xor_sync(0xffffffffu, pua, 1);
        pub += __shfl_xor_sync(0xffffffffu, pub, 1);
        pra += __shfl_xor_sync(0xffffffffu, pra, 1);
        prb += __shfl_xor_sync(0xffffffffu, prb, 1);

        const float gu_a = sigmoid_f(pua + xu_a + bun);
        const float gu_b = sigmoid_f(pub + xu_b + bun);
        const float h_a  = sigmoid_f(pra + xr_a + brn) * c_a;
        const float h_b  = sigmoid_f(prb + xr_b + brn) * c_b;

        // broadcast this thread's h value to all 4 CTAs
        const float hv = kh ? h_b : h_a;
        #pragma unroll
        for (int d = 0; d < 4; d++) st_cluster_f32(h_dst[d], hv);
        __syncthreads();
        if (tid < 4) mbar_arrive_rank(barH, (uint32_t)tid);
        mbar_wait_parity(barH, ph);

        // ---- phase B: pre_c = (g_r*c) @ wcc[:, n] ----
        unsigned long long aCa0 = 0, aCa1 = 0, aCb0 = 0, aCb1 = 0;
        #pragma unroll 8
        for (int i = 0; i < 32; i++) {
            const int o = i * 8;
            ulonglong2 wc = *(const ulonglong2*)(wcp + o);
            ulonglong2 ha = *(const ulonglong2*)(hap + o);
            ulonglong2 hb = *(const ulonglong2*)(hbp + o);
            FFMA2(aCa0, ha.x, wc.x); FFMA2(aCa1, ha.y, wc.y);
            FFMA2(aCb0, hb.x, wc.x); FFMA2(aCb1, hb.y, wc.y);
        }
        float pca = hsum2(aCa0) + hsum2(aCa1);
        float pcb = hsum2(aCb0) + hsum2(aCb1);
        pca += __shfl_xor_sync(0xffffffffu, pca, 1);
        pcb += __shfl_xor_sync(0xffffffffu, pcb, 1);

        const float cand_a = tanhf(pca + xc_a + bcn);
        const float cand_b = tanhf(pcb + xc_b + bcn);
        c_a = fmaf(gu_a, cand_a - c_a, c_a);
        c_b = fmaf(gu_b, cand_b - c_b, c_b);

        // broadcast this thread's c value to all 4 CTAs
        const float cv = kh ? c_b : c_a;
        #pragma unroll
        for (int d = 0; d < 4; d++) st_cluster_f32(c_dst[d], cv);
        __syncthreads();
        if (tid < 4) mbar_arrive_rank(barC, (uint32_t)tid);
        mbar_wait_parity(barC, ph);
    }

    out[(size_t)(r0 + myrow) * UDIM + n_g] = kh ? c_b : c_a;
    CLUSTER_SYNC_();
}

// =====================================================================
// Launch
// Inputs (metadata order):
//  0:x [256,512,256]  1:a0 [256,256]
//  2:wcx 3:wcc 4:bc   5:wux 6:wuc 7:bu   8:wrx 9:wrc 10:br
// =====================================================================
extern "C" void kernel_launch(void* const* d_in, const int* in_sizes, int n_in,
                              void* d_out, int out_size)
{
    const float* x   = (const float*)d_in[0];
    const float* a0  = (const float*)d_in[1];
    const float* wcx = (const float*)d_in[2];
    const float* wcc = (const float*)d_in[3];
    const float* bc  = (const float*)d_in[4];
    const float* wux = (const float*)d_in[5];
    const float* wuc = (const float*)d_in[6];
    const float* bu  = (const float*)d_in[7];
    const float* wrx = (const float*)d_in[8];
    const float* wrc = (const float*)d_in[9];
    const float* br  = (const float*)d_in[10];
    float* out = (float*)d_out;

    cudaFuncSetAttribute(gru_scan3,
                         cudaFuncAttributeMaxDynamicSharedMemorySize, SM_BYTES);

    // Phase 1: x projections (z=0 -> wux, z=1 -> wrx, z=2 -> wcx)
    dim3 g1((MDIM * TDIM) / 128, UDIM / 128, 3);
    xproj_kernel<<<g1, 256>>>(x, wux, wrx, wcx);

    // Phase 2: sequential scan — 32 clusters x 4 CTAs, 512 thr
    gru_scan3<<<128, 512, SM_BYTES>>>(wuc, wrc, wcc, bu, br, bc, a0, out);
}

// round 10
// speedup vs baseline: 1.0016x; 1.0016x over previous
#include <cuda_runtime.h>
#include <cuda_bf16.h>
#include <cstdint>

// Problem dims
#define MDIM 256
#define TDIM 512
#define NXDIM 256
#define UDIM 256

// Scratch for x-projections: 3 matrices x [T][M][U] fp32 = 402 MB.
#define XP_STRIDE (33554432ULL) // 512*256*256
__device__ float g_xp[3ULL * XP_STRIDE];

// ---------------- packed f32x2 helpers ----------------
#define FFMA2(c_, a_, b_) \
    asm volatile("fma.rn.f32x2 %0, %1, %2, %0;" : "+l"(c_) : "l"(a_), "l"(b_))

__device__ __forceinline__ unsigned long long dup2(float a) {
    unsigned long long r;
    asm("mov.b64 %0, {%1, %1};" : "=l"(r) : "f"(a));
    return r;
}
__device__ __forceinline__ void unpack2(float& lo, float& hi, unsigned long long v) {
    asm("mov.b64 {%0, %1}, %2;" : "=f"(lo), "=f"(hi) : "l"(v));
}
__device__ __forceinline__ float hsum2(unsigned long long v) {
    float lo, hi; unpack2(lo, hi, v); return lo + hi;
}

// ---------------- cluster / DSMEM helpers ----------------
__device__ __forceinline__ uint32_t smem_u32(const void* p) {
    uint32_t a;
    asm("{ .reg .u64 t; cvta.to.shared.u64 t, %1; cvt.u32.u64 %0, t; }"
        : "=r"(a) : "l"(p));
    return a;
}
__device__ __forceinline__ uint32_t mapa_rank(uint32_t addr, uint32_t rank) {
    uint32_t r;
    asm("mapa.shared::cluster.u32 %0, %1, %2;" : "=r"(r) : "r"(addr), "r"(rank));
    return r;
}
__device__ __forceinline__ void st_cluster_f32(uint32_t addr, float v) {
    asm volatile("st.shared::cluster.f32 [%0], %1;" :: "r"(addr), "f"(v) : "memory");
}
__device__ __forceinline__ uint32_t ctarank() {
    uint32_t r; asm("mov.u32 %0, %%cluster_ctarank;" : "=r"(r)); return r;
}
#define CLUSTER_SYNC_() do { \
    asm volatile("barrier.cluster.arrive.aligned;" ::: "memory"); \
    asm volatile("barrier.cluster.wait.aligned;" ::: "memory"); } while (0)

// mbarrier: init (count arrivals), remote release-arrive, local acquire-wait
__device__ __forceinline__ void mbar_init(uint32_t bar, uint32_t cnt) {
    asm volatile("mbarrier.init.shared.b64 [%0], %1;" :: "r"(bar), "r"(cnt) : "memory");
}
__device__ __forceinline__ void mbar_arrive_rank(uint32_t local_bar, uint32_t rank) {
    uint32_t remote = mapa_rank(local_bar, rank);
    asm volatile("mbarrier.arrive.release.cluster.shared::cluster.b64 _, [%0];"
                 :: "r"(remote) : "memory");
}
__device__ __forceinline__ void mbar_wait_parity(uint32_t bar, uint32_t parity) {
    uint32_t done;
    asm volatile(
        "{\n\t.reg .pred p;\n\t"
        "mbarrier.try_wait.parity.acquire.cluster.shared::cta.b64 p, [%1], %2;\n\t"
        "selp.b32 %0, 1, 0, p;\n\t}"
        : "=r"(done) : "r"(bar), "r"(parity) : "memory");
    if (!done) {
        asm volatile(
            "{\n\t.reg .pred P1;\n\t"
            "WLOOP_%=:\n\t"
            "mbarrier.try_wait.parity.acquire.cluster.shared::cta.b64 P1, [%0], %1, 0x989680;\n\t"
            "@P1 bra.uni WDONE_%=;\n\t"
            "bra.uni WLOOP_%=;\n\t"
            "WDONE_%=:\n\t}"
            :: "r"(bar), "r"(parity) : "memory");
    }
}

// =====================================================================
// Phase 1: x projections (unchanged — ~1.06 ms, ~72% of fp32x2 peak).
// =====================================================================
__global__ __launch_bounds__(256, 1)
void xproj_kernel(const float* __restrict__ x,
                  const float* __restrict__ w_u,
                  const float* __restrict__ w_r,
                  const float* __restrict__ w_c)
{
    const float* __restrict__ w =
        (blockIdx.z == 0) ? w_u : ((blockIdx.z == 1) ? w_r : w_c);
    float* __restrict__ outp = g_xp + (size_t)blockIdx.z * XP_STRIDE;

    const int tid = threadIdx.x;
    const int g0  = blockIdx.x * 128;
    const int t   = g0 >> 8;
    const int m0  = g0 & 255;
    const int n0  = blockIdx.y * 128;

    __shared__ float As[16][132];
    __shared__ float Bs[16][128];

    const int tx = tid & 15;
    const int ty = tid >> 4;

    unsigned long long acc[8][4];
    #pragma unroll
    for (int i = 0; i < 8; i++)
        #pragma unroll
        for (int j = 0; j < 4; j++) acc[i][j] = 0ULL;

    for (int kk = 0; kk < NXDIM; kk += 16) {
        #pragma unroll
        for (int l = 0; l < 2; l++) {
            int f  = tid + l * 256;
            int i  = f >> 2;
            int kv = (f & 3) * 4;
            const float4 v = *(const float4*)(x +
                ((size_t)(m0 + i) * TDIM + t) * NXDIM + kk + kv);
            As[kv + 0][i] = v.x;
            As[kv + 1][i] = v.y;
            As[kv + 2][i] = v.z;
            As[kv + 3][i] = v.w;
        }
        #pragma unroll
        for (int l = 0; l < 2; l++) {
            int f  = tid + l * 256;
            int k  = f >> 5;
            int nn = (f & 31) * 4;
            *(float4*)&Bs[k][nn] =
                *(const float4*)(w + (size_t)(kk + k) * UDIM + n0 + nn);
        }
        __syncthreads();

        #pragma unroll
        for (int k = 0; k < 16; k++) {
            float4 a0v = *(const float4*)&As[k][ty * 8];
            float4 a1v = *(const float4*)&As[k][ty * 8 + 4];
            const unsigned long long* bp =
                (const unsigned long long*)&Bs[k][tx * 8];
            unsigned long long b0 = bp[0], b1 = bp[1], b2 = bp[2], b3 = bp[3];
            float av[8] = {a0v.x, a0v.y, a0v.z, a0v.w,
                           a1v.x, a1v.y, a1v.z, a1v.w};
            #pragma unroll
            for (int i = 0; i < 8; i++) {
                unsigned long long ad = dup2(av[i]);
                FFMA2(acc[i][0], ad, b0);
                FFMA2(acc[i][1], ad, b1);
                FFMA2(acc[i][2], ad, b2);
                FFMA2(acc[i][3], ad, b3);
            }
        }
        __syncthreads();
    }

    #pragma unroll
    for (int i = 0; i < 8; i++) {
        int g = g0 + ty * 8 + i;
        float o[8];
        unpack2(o[0], o[1], acc[i][0]);
        unpack2(o[2], o[3], acc[i][1]);
        unpack2(o[4], o[5], acc[i][2]);
        unpack2(o[6], o[7], acc[i][3]);
        float* op = outp + (size_t)g * UDIM + n0 + tx * 8;
        *(float4*)(op)     = make_float4(o[0], o[1], o[2], o[3]);
        *(float4*)(op + 4) = make_float4(o[4], o[5], o[6], o[7]);
    }
}

// =====================================================================
// Phase 2: GRU scan — 32 clusters x 4 CTAs, 512 threads/CTA.
//   Thread = (n_l 0..63, rp 0..3, kh 0..1): 2 rows (rp, rp+4), half
//   the k range via 4-float interleave (k = i*8 + kh*4).  Stride 264
//   keeps every 8-lane LDS128 phase bank-conflict-free.
//   Per step: phase A (u,r gates) -> DSMEM bcast h -> mbar sync
//           -> phase B (candidate) -> DSMEM bcast c -> mbar sync.
// =====================================================================
#define WST 264
#define OFF_WU 16
#define OFF_WR (16 + 64 * WST)
#define OFF_WC (16 + 128 * WST)
#define OFF_C  (16 + 192 * WST)
#define OFF_H  (16 + 200 * WST)
#define SM_FLOATS (16 + 208 * WST)     // 54928 floats
#define SM_BYTES (SM_FLOATS * 4)       // 219712 bytes

__device__ __forceinline__ float sigmoid_f(float z) {
    return 1.0f / (1.0f + __expf(-z));
}

__global__ __launch_bounds__(512, 1) __cluster_dims__(4, 1, 1)
void gru_scan3(const float* __restrict__ wuc,
               const float* __restrict__ wrc,
               const float* __restrict__ wcc,
               const float* __restrict__ bu,
               const float* __restrict__ br,
               const float* __restrict__ bc,
               const float* __restrict__ a0,
               float* __restrict__ out)
{
    extern __shared__ float sm[];
    float* wu_s = sm + OFF_WU;
    float* wr_s = sm + OFF_WR;
    float* wc_s = sm + OFF_WC;
    float* c_s  = sm + OFF_C;
    float* h_s  = sm + OFF_H;

    const int tid = threadIdx.x;
    const uint32_t rank = ctarank();
    const int n0 = (int)rank * 64;
    const int r0 = (blockIdx.x >> 2) * 8;

    const int n_l = tid >> 3;
    const int rp  = (tid >> 1) & 3;
    const int kh  = tid & 1;
    const int ra  = rp, rb = rp + 4;
    const int n_g = n0 + n_l;
    const int kofs = kh * 4;

    const uint32_t barH = smem_u32(sm);       // 8 bytes
    const uint32_t barC = smem_u32(sm) + 8;   // 8 bytes

    if (tid == 0) { mbar_init(barH, 4); mbar_init(barC, 4); }

    // ---- load weight slices transposed: wT[n_l][k] = W[k][n0+n_l] ----
    for (int i = tid; i < 64 * 256; i += 512) {
        int k  = i >> 6;
        int nl = i & 63;
        wu_s[nl * WST + k] = wuc[k * UDIM + n0 + nl];
        wr_s[nl * WST + k] = wrc[k * UDIM + n0 + nl];
        wc_s[nl * WST + k] = wcc[k * UDIM + n0 + nl];
    }
    // ---- init c_s (8 rows) ----
    for (int i = tid; i < 8 * 256; i += 512) {
        int r = i >> 8, k = i & 255;
        c_s[r * WST + k] = a0[(size_t)(r0 + r) * UDIM + k];
    }
    float c_a = a0[(size_t)(r0 + ra) * UDIM + n_g];
    float c_b = a0[(size_t)(r0 + rb) * UDIM + n_g];
    const float bun = bu[n_g], brn = br[n_g], bcn = bc[n_g];

    // ---- DSMEM broadcast targets: this thread publishes ONE value
    //      (kh==0 -> row ra, kh==1 -> row rb) to all 4 ranks ----
    const int myrow = kh ? rb : ra;
    uint32_t h_loc = smem_u32(&h_s[myrow * WST + n_g]);
    uint32_t c_loc = smem_u32(&c_s[myrow * WST + n_g]);
    uint32_t h_dst[4], c_dst[4];
    #pragma unroll
    for (int d = 0; d < 4; d++) {
        h_dst[d] = mapa_rank(h_loc, d);
        c_dst[d] = mapa_rank(c_loc, d);
    }

    __syncthreads();
    CLUSTER_SYNC_();   // mbarrier inits + weight/c tiles visible cluster-wide

    const float* __restrict__ xu = g_xp;
    const float* __restrict__ xr = g_xp + XP_STRIDE;
    const float* __restrict__ xc = g_xp + 2ULL * XP_STRIDE;

    const float* wup = wu_s + n_l * WST + kofs;
    const float* wrp = wr_s + n_l * WST + kofs;
    const float* wcp = wc_s + n_l * WST + kofs;
    const float* cap = c_s + ra * WST + kofs;
    const float* cbp = c_s + rb * WST + kofs;
    const float* hap = h_s + ra * WST + kofs;
    const float* hbp = h_s + rb * WST + kofs;

    for (int t = 0; t < TDIM; t++) {
        const uint32_t ph = (uint32_t)(t & 1);

        // prefetch x-projection terms (hidden under phase A)
        const size_t xb = ((size_t)t * MDIM + r0) * UDIM + n_g;
        const float xu_a = __ldg(xu + xb + (size_t)ra * UDIM);
        const float xu_b = __ldg(xu + xb + (size_t)rb * UDIM);
        const float xr_a = __ldg(xr + xb + (size_t)ra * UDIM);
        const float xr_b = __ldg(xr + xb + (size_t)rb * UDIM);
        const float xc_a = __ldg(xc + xb + (size_t)ra * UDIM);
        const float xc_b = __ldg(xc + xb + (size_t)rb * UDIM);

        // ---- phase A: pre_u, pre_r (this thread's k-half) ----
        unsigned long long aUa0 = 0, aUa1 = 0, aUb0 = 0, aUb1 = 0;
        unsigned long long aRa0 = 0, aRa1 = 0, aRb0 = 0, aRb1 = 0;
        #pragma unroll 8
        for (int i = 0; i < 32; i++) {
            const int o = i * 8;   // floats; k = i*8 + kh*4 via kofs
            ulonglong2 wu = *(const ulonglong2*)(wup + o);
            ulonglong2 wr = *(const ulonglong2*)(wrp + o);
            ulonglong2 ca = *(const ulonglong2*)(cap + o);
            ulonglong2 cb = *(const ulonglong2*)(cbp + o);
            FFMA2(aUa0, ca.x, wu.x); FFMA2(aUa1, ca.y, wu.y);
            FFMA2(aUb0, cb.x, wu.x); FFMA2(aUb1, cb.y, wu.y);
            FFMA2(aRa0, ca.x, wr.x); FFMA2(aRa1, ca.y, wr.y);
            FFMA2(aRb0, cb.x, wr.x); FFMA2(aRb1, cb.y, wr.y);
        }
        float pua = hsum2(aUa0) + hsum2(aUa1);
        float pub = hsum2(aUb0) + hsum2(aUb1);
        float pra = hsum2(aRa0) + hsum2(aRa1);
        float prb = hsum2(aRb0) + hsum2(aRb1);
        pua += __shfl_xor_sync(0xffffffffu, pua, 1);
        pub += __shfl_xor_sync(0xffffffffu, pub, 1);
        pra += __shfl_xor_sync(0xffffffffu, pra, 1);
        prb += __shfl_xor_sync(0xffffffffu, prb, 1);

        const float gu_a = sigmoid_f(pua + xu_a + bun);
        const float gu_b = sigmoid_f(pub + xu_b + bun);
        const float h_a  = sigmoid_f(pra + xr_a + brn) * c_a;
        const float h_b  = sigmoid_f(prb + xr_b + brn) * c_b;

        // broadcast this thread's h value to all 4 CTAs
        const float hv = kh ? h_b : h_a;
        #pragma unroll
        for (int d = 0; d < 4; d++) st_cluster_f32(h_dst[d], hv);
        __syncthreads();
        if (tid < 4) mbar_arrive_rank(barH, (uint32_t)tid);
        mbar_wait_parity(barH, ph);

        // ---- phase B: pre_c = (g_r*c) @ wcc[:, n] ----
        unsigned long long aCa0 = 0, aCa1 = 0, aCb0 = 0, aCb1 = 0;
        #pragma unroll 8
        for (int i = 0; i < 32; i++) {
            const int o = i * 8;
            ulonglong2 wc = *(const ulonglong2*)(wcp + o);
            ulonglong2 ha = *(const ulonglong2*)(hap + o);
            ulonglong2 hb = *(const ulonglong2*)(hbp + o);
            FFMA2(aCa0, ha.x, wc.x); FFMA2(aCa1, ha.y, wc.y);
            FFMA2(aCb0, hb.x, wc.x); FFMA2(aCb1, hb.y, wc.y);
        }
        float pca = hsum2(aCa0) + hsum2(aCa1);
        float pcb = hsum2(aCb0) + hsum2(aCb1);
        pca += __shfl_xor_sync(0xffffffffu, pca, 1);
        pcb += __shfl_xor_sync(0xffffffffu, pcb, 1);

        const float cand_a = tanhf(pca + xc_a + bcn);
        const float cand_b = tanhf(pcb + xc_b + bcn);
        c_a = fmaf(gu_a, cand_a - c_a, c_a);
        c_b = fmaf(gu_b, cand_b - c_b, c_b);

        // broadcast this thread's c value to all 4 CTAs
        const float cv = kh ? c_b : c_a;
        #pragma unroll
        for (int d = 0; d < 4; d++) st_cluster_f32(c_dst[d], cv);
        __syncthreads();
        if (tid < 4) mbar_arrive_rank(barC, (uint32_t)tid);
        mbar_wait_parity(barC, ph);
    }

    out[(size_t)(r0 + myrow) * UDIM + n_g] = kh ? c_b : c_a;
    CLUSTER_SYNC_();
}

// =====================================================================
// Launch
// Inputs (metadata order):
//  0:x [256,512,256]  1:a0 [256,256]
//  2:wcx 3:wcc 4:bc   5:wux 6:wuc 7:bu   8:wrx 9:wrc 10:br
// =====================================================================
extern "C" void kernel_launch(void* const* d_in, const int* in_sizes, int n_in,
                              void* d_out, int out_size)
{
    const float* x   = (const float*)d_in[0];
    const float* a0  = (const float*)d_in[1];
    const float* wcx = (const float*)d_in[2];
    const float* wcc = (const float*)d_in[3];
    const float* bc  = (const float*)d_in[4];
    const float* wux = (const float*)d_in[5];
    const float* wuc = (const float*)d_in[6];
    const float* bu  = (const float*)d_in[7];
    const float* wrx = (const float*)d_in[8];
    const float* wrc = (const float*)d_in[9];
    const float* br  = (const float*)d_in[10];
    float* out = (float*)d_out;

    cudaFuncSetAttribute(gru_scan3,
                         cudaFuncAttributeMaxDynamicSharedMemorySize, SM_BYTES);

    // Phase 1: x projections (z=0 -> wux, z=1 -> wrx, z=2 -> wcx)
    dim3 g1((MDIM * TDIM) / 128, UDIM / 128, 3);
    xproj_kernel<<<g1, 256>>>(x, wux, wrx, wcx);

    // Phase 2: sequential scan — 32 clusters x 4 CTAs, 512 thr
    gru_scan3<<<128, 512, SM_BYTES>>>(wuc, wrc, wcc, bu, br, bc, a0, out);
}

// round 11
// speedup vs baseline: 1.2864x; 1.2844x over previous
#include <cuda_runtime.h>
#include <cuda_bf16.h>
#include <cstdint>

// Problem dims
#define MDIM 256
#define TDIM 512
#define NXDIM 256
#define UDIM 256

// Scratch for x-projections: 3 matrices x [T][M][U] fp32 = 402 MB.
#define XP_STRIDE (33554432ULL) // 512*256*256
__device__ float g_xp[3ULL * XP_STRIDE];

// ---------------- packed f32x2 helpers ----------------
#define FFMA2(c_, a_, b_) \
    asm volatile("fma.rn.f32x2 %0, %1, %2, %0;" : "+l"(c_) : "l"(a_), "l"(b_))
#define ADD2(o_, a_, b_) \
    asm("add.rn.f32x2 %0, %1, %2;" : "=l"(o_) : "l"(a_), "l"(b_))

__device__ __forceinline__ unsigned long long dup2(float a) {
    unsigned long long r;
    asm("mov.b64 %0, {%1, %1};" : "=l"(r) : "f"(a));
    return r;
}
__device__ __forceinline__ unsigned long long pack2(float lo, float hi) {
    unsigned long long r;
    asm("mov.b64 %0, {%1, %2};" : "=l"(r) : "f"(lo), "f"(hi));
    return r;
}
__device__ __forceinline__ void unpack2(float& lo, float& hi, unsigned long long v) {
    asm("mov.b64 {%0, %1}, %2;" : "=f"(lo), "=f"(hi) : "l"(v));
}

// ---------------- cluster / DSMEM helpers ----------------
__device__ __forceinline__ uint32_t smem_u32(const void* p) {
    uint32_t a;
    asm("{ .reg .u64 t; cvta.to.shared.u64 t, %1; cvt.u32.u64 %0, t; }"
        : "=r"(a) : "l"(p));
    return a;
}
__device__ __forceinline__ uint32_t mapa_rank(uint32_t addr, uint32_t rank) {
    uint32_t r;
    asm("mapa.shared::cluster.u32 %0, %1, %2;" : "=r"(r) : "r"(addr), "r"(rank));
    return r;
}
__device__ __forceinline__ void st_cluster_u64(uint32_t addr, unsigned long long v) {
    asm volatile("st.shared::cluster.u64 [%0], %1;" :: "r"(addr), "l"(v) : "memory");
}
__device__ __forceinline__ uint32_t ctarank() {
    uint32_t r; asm("mov.u32 %0, %%cluster_ctarank;" : "=r"(r)); return r;
}
#define CLUSTER_SYNC_() do { \
    asm volatile("barrier.cluster.arrive.aligned;" ::: "memory"); \
    asm volatile("barrier.cluster.wait.aligned;" ::: "memory"); } while (0)

__device__ __forceinline__ void mbar_init(uint32_t bar, uint32_t cnt) {
    asm volatile("mbarrier.init.shared.b64 [%0], %1;" :: "r"(bar), "r"(cnt) : "memory");
}
__device__ __forceinline__ void mbar_arrive_rank(uint32_t local_bar, uint32_t rank) {
    uint32_t remote = mapa_rank(local_bar, rank);
    asm volatile("mbarrier.arrive.release.cluster.shared::cluster.b64 _, [%0];"
                 :: "r"(remote) : "memory");
}
__device__ __forceinline__ void mbar_wait_parity(uint32_t bar, uint32_t parity) {
    uint32_t done;
    asm volatile(
        "{\n\t.reg .pred p;\n\t"
        "mbarrier.try_wait.parity.acquire.cluster.shared::cta.b64 p, [%1], %2;\n\t"
        "selp.b32 %0, 1, 0, p;\n\t}"
        : "=r"(done) : "r"(bar), "r"(parity) : "memory");
    if (!done) {
        asm volatile(
            "{\n\t.reg .pred P1;\n\t"
            "WLOOP_%=:\n\t"
            "mbarrier.try_wait.parity.acquire.cluster.shared::cta.b64 P1, [%0], %1, 0x989680;\n\t"
            "@P1 bra.uni WDONE_%=;\n\t"
            "bra.uni WLOOP_%=;\n\t"
            "WDONE_%=:\n\t}"
            :: "r"(bar), "r"(parity) : "memory");
    }
}

// 64-bit xor shfl (2x SHFL.b32)
__device__ __forceinline__ unsigned long long shfl64(unsigned long long v, int m) {
    return __shfl_xor_sync(0xffffffffu, v, m);
}

// Butterfly reduction step: v[0..2N) -> v[0..N).  sel = this lane keeps
// the upper half.  Partner (lane^m) sends the half this lane keeps.
template<int N>
__device__ __forceinline__ void redstep(unsigned long long* v, bool sel, int m) {
    #pragma unroll
    for (int i = 0; i < N; i++) {
        unsigned long long mine = sel ? v[i + N] : v[i];
        unsigned long long send = sel ? v[i] : v[i + N];
        unsigned long long r = shfl64(send, m);
        ADD2(v[i], mine, r);
    }
}

// =====================================================================
// Phase 1: x projections (unchanged — validated at ~1.06 ms).
// =====================================================================
__global__ __launch_bounds__(256, 1)
void xproj_kernel(const float* __restrict__ x,
                  const float* __restrict__ w_u,
                  const float* __restrict__ w_r,
                  const float* __restrict__ w_c)
{
    const float* __restrict__ w =
        (blockIdx.z == 0) ? w_u : ((blockIdx.z == 1) ? w_r : w_c);
    float* __restrict__ outp = g_xp + (size_t)blockIdx.z * XP_STRIDE;

    const int tid = threadIdx.x;
    const int g0  = blockIdx.x * 128;
    const int t   = g0 >> 8;
    const int m0  = g0 & 255;
    const int n0  = blockIdx.y * 128;

    __shared__ float As[16][132];
    __shared__ float Bs[16][128];

    const int tx = tid & 15;
    const int ty = tid >> 4;

    unsigned long long acc[8][4];
    #pragma unroll
    for (int i = 0; i < 8; i++)
        #pragma unroll
        for (int j = 0; j < 4; j++) acc[i][j] = 0ULL;

    for (int kk = 0; kk < NXDIM; kk += 16) {
        #pragma unroll
        for (int l = 0; l < 2; l++) {
            int f  = tid + l * 256;
            int i  = f >> 2;
            int kv = (f & 3) * 4;
            const float4 v = *(const float4*)(x +
                ((size_t)(m0 + i) * TDIM + t) * NXDIM + kk + kv);
            As[kv + 0][i] = v.x;
            As[kv + 1][i] = v.y;
            As[kv + 2][i] = v.z;
            As[kv + 3][i] = v.w;
        }
        #pragma unroll
        for (int l = 0; l < 2; l++) {
            int f  = tid + l * 256;
            int k  = f >> 5;
            int nn = (f & 31) * 4;
            *(float4*)&Bs[k][nn] =
                *(const float4*)(w + (size_t)(kk + k) * UDIM + n0 + nn);
        }
        __syncthreads();

        #pragma unroll
        for (int k = 0; k < 16; k++) {
            float4 a0v = *(const float4*)&As[k][ty * 8];
            float4 a1v = *(const float4*)&As[k][ty * 8 + 4];
            const unsigned long long* bp =
                (const unsigned long long*)&Bs[k][tx * 8];
            unsigned long long b0 = bp[0], b1 = bp[1], b2 = bp[2], b3 = bp[3];
            float av[8] = {a0v.x, a0v.y, a0v.z, a0v.w,
                           a1v.x, a1v.y, a1v.z, a1v.w};
            #pragma unroll
            for (int i = 0; i < 8; i++) {
                unsigned long long ad = dup2(av[i]);
                FFMA2(acc[i][0], ad, b0);
                FFMA2(acc[i][1], ad, b1);
                FFMA2(acc[i][2], ad, b2);
                FFMA2(acc[i][3], ad, b3);
            }
        }
        __syncthreads();
    }

    #pragma unroll
    for (int i = 0; i < 8; i++) {
        int g = g0 + ty * 8 + i;
        float o[8];
        unpack2(o[0], o[1], acc[i][0]);
        unpack2(o[2], o[3], acc[i][1]);
        unpack2(o[4], o[5], acc[i][2]);
        unpack2(o[6], o[7], acc[i][3]);
        float* op = outp + (size_t)g * UDIM + n0 + tx * 8;
        *(float4*)(op)     = make_float4(o[0], o[1], o[2], o[3]);
        *(float4*)(op + 4) = make_float4(o[4], o[5], o[6], o[7]);
    }
}

// =====================================================================
// Phase 2: GRU scan — 32 clusters x 4 CTAs, 128 threads/CTA.
//   Thread = (ng 0..15 -> cols nbase..nbase+3, ks 0..7 -> k in {ks+8j}).
//   Lane = ks + 8*(ng&3): ks varies inside every 8-lane LDS phase, so
//   every LDS.128 moves 128 distinct conflict-free bytes.
//   Weights k-major: wu/wr row stride 68 (ks*4 mod 32 distinct),
//   wc stride 76 (ks*12 mod 32 distinct).  c rows live in wc row pads
//   (words 64..71 = c[k][row0..7]); h rows 0-3 in wu pads, 4-7 in wr
//   pads.  Register tile 4 cols x 8 rows x 32 k; 8-way k-reduction via
//   3-round shfl butterfly; lane ks ends owning col nbase+(ks>>1),
//   rows 4*(ks&1)..+3, and DSMEM-broadcasts h / c_new to all 4 ranks.
// =====================================================================
#define NSTW 68
#define NSTC 76
#define OWU 8
#define OWR (OWU + 256 * NSTW)        // 17416
#define OWC (OWR + 256 * NSTW)        // 34824
#define SMF (OWC + 256 * NSTC)        // 54280 floats
#define SMB (SMF * 4)                 // 217120 bytes

__device__ __forceinline__ float sigmoid_f(float z) {
    return 1.0f / (1.0f + __expf(-z));
}

__global__ __launch_bounds__(128, 1) __cluster_dims__(4, 1, 1)
void gru_scan4(const float* __restrict__ wuc,
               const float* __restrict__ wrc,
               const float* __restrict__ wcc,
               const float* __restrict__ bu,
               const float* __restrict__ br,
               const float* __restrict__ bc,
               const float* __restrict__ a0,
               float* __restrict__ out)
{
    extern __shared__ float sm[];
    float* wu_s = sm + OWU;
    float* wr_s = sm + OWR;
    float* wc_s = sm + OWC;

    const int tid = threadIdx.x;
    const uint32_t rank = ctarank();
    const int n0 = (int)rank * 64;
    const int r0 = (blockIdx.x >> 2) * 8;

    const int ks    = tid & 7;
    const int ng    = tid >> 3;
    const int nbase = ng * 4;
    const bool b2 = (ks & 4) != 0, b1 = (ks & 2) != 0, b0 = (ks & 1) != 0;
    const int rh    = ks & 1;               // owned row-half after reduce
    const int col_g = n0 + nbase + (ks >> 1);  // owned unit
    const int m_own = r0 + rh * 4;          // owned rows m_own..m_own+3

    const uint32_t barH = smem_u32(sm);
    const uint32_t barC = barH + 8;
    if (tid == 0) { mbar_init(barH, 4); mbar_init(barC, 4); }

    // ---- weights k-major into smem (each word written once) ----
    for (int i = tid; i < 64 * 256; i += 128) {
        int k = i >> 6, n = i & 63;
        wu_s[k * NSTW + n] = wuc[k * UDIM + n0 + n];
        wr_s[k * NSTW + n] = wrc[k * UDIM + n0 + n];
        wc_s[k * NSTC + n] = wcc[k * UDIM + n0 + n];
    }
    // ---- c init into wc pads: c[u][r] at wc_s[u*76 + 64 + r] ----
    for (int i = tid; i < 256 * 8; i += 128) {
        int u = i >> 3, r = i & 7;
        wc_s[u * NSTC + 64 + r] = a0[(size_t)(r0 + r) * UDIM + u];
    }
    float cme[4];
    #pragma unroll
    for (int i = 0; i < 4; i++)
        cme[i] = a0[(size_t)(m_own + i) * UDIM + col_g];
    const float bun = bu[col_g], brn = br[col_g], bcn = bc[col_g];

    // ---- DSMEM broadcast targets ----
    uint32_t hbase = smem_u32((rh ? wr_s : wu_s) + col_g * NSTW + 64);
    uint32_t cbase = smem_u32(wc_s + col_g * NSTC + 64 + 4 * rh);
    uint32_t hdst[4], cdst[4];
    #pragma unroll
    for (int d = 0; d < 4; d++) {
        hdst[d] = mapa_rank(hbase, d);
        cdst[d] = mapa_rank(cbase, d);
    }

    __syncthreads();
    CLUSTER_SYNC_();

    const float* __restrict__ xu = g_xp;
    const float* __restrict__ xr = g_xp + XP_STRIDE;
    const float* __restrict__ xc = g_xp + 2ULL * XP_STRIDE;

    const float* wup = wu_s + ks * NSTW + nbase;
    const float* wrp = wr_s + ks * NSTW + nbase;
    const float* wcp = wc_s + ks * NSTC + nbase;
    const float* cpp = wc_s + ks * NSTC + 64;   // c rows
    const float* hup = wu_s + ks * NSTW + 64;   // h rows 0..3
    const float* hrp = wr_s + ks * NSTW + 64;   // h rows 4..7

    for (int t = 0; t < TDIM; t++) {
        const uint32_t ph = (uint32_t)(t & 1);

        // prefetch x-projection terms for owned (col, 4 rows)
        const size_t xo = (size_t)t * (MDIM * UDIM) + (size_t)m_own * UDIM + col_g;
        float xu4[4], xr4[4], xc4[4];
        #pragma unroll
        for (int i = 0; i < 4; i++) {
            xu4[i] = __ldg(xu + xo + i * UDIM);
            xr4[i] = __ldg(xr + xo + i * UDIM);
            xc4[i] = __ldg(xc + xo + i * UDIM);
        }

        // ================= phase A: pre_u, pre_r =================
        unsigned long long aU[16], aR[16];   // [c*4 + q]
        #pragma unroll
        for (int i = 0; i < 16; i++) { aU[i] = 0ULL; aR[i] = 0ULL; }

        #pragma unroll 2
        for (int j = 0; j < 32; j++) {
            const float4 wu4 = *(const float4*)(wup + j * (8 * NSTW));
            const float4 wr4 = *(const float4*)(wrp + j * (8 * NSTW));
            const ulonglong2 cA = *(const ulonglong2*)(cpp + j * (8 * NSTC));
            const ulonglong2 cB = *(const ulonglong2*)(cpp + j * (8 * NSTC) + 4);
            const unsigned long long c2[4] = {cA.x, cA.y, cB.x, cB.y};
            const float wuf[4] = {wu4.x, wu4.y, wu4.z, wu4.w};
            const float wrf[4] = {wr4.x, wr4.y, wr4.z, wr4.w};
            #pragma unroll
            for (int c = 0; c < 4; c++) {
                const unsigned long long du = dup2(wuf[c]);
                const unsigned long long dr = dup2(wrf[c]);
                #pragma unroll
                for (int q = 0; q < 4; q++) {
                    FFMA2(aU[c * 4 + q], c2[q], du);
                    FFMA2(aR[c * 4 + q], c2[q], dr);
                }
            }
        }

        // 8-way k-reduce: cols (bits b2,b1) then row-half (bit b0)
        redstep<8>(aU, b2, 4);  redstep<8>(aR, b2, 4);
        redstep<4>(aU, b1, 2);  redstep<4>(aR, b1, 2);
        redstep<2>(aU, b0, 1);  redstep<2>(aR, b0, 1);

        float pu[4], pr[4];
        unpack2(pu[0], pu[1], aU[0]); unpack2(pu[2], pu[3], aU[1]);
        unpack2(pr[0], pr[1], aR[0]); unpack2(pr[2], pr[3], aR[1]);

        float gu[4], h4[4];
        #pragma unroll
        for (int i = 0; i < 4; i++) {
            gu[i] = sigmoid_f(pu[i] + xu4[i] + bun);
            h4[i] = sigmoid_f(pr[i] + xr4[i] + brn) * cme[i];
        }

        // broadcast h (owned col, 4 rows) to all 4 ranks
        {
            const unsigned long long h01 = pack2(h4[0], h4[1]);
            const unsigned long long h23 = pack2(h4[2], h4[3]);
            #pragma unroll
            for (int d = 0; d < 4; d++) {
                st_cluster_u64(hdst[d], h01);
                st_cluster_u64(hdst[d] + 8, h23);
            }
        }
        __syncthreads();
        if (tid < 4) mbar_arrive_rank(barH, (uint32_t)tid);
        mbar_wait_parity(barH, ph);

        // ================= phase B: pre_c =================
        unsigned long long aC[16];
        #pragma unroll
        for (int i = 0; i < 16; i++) aC[i] = 0ULL;

        #pragma unroll 2
        for (int j = 0; j < 32; j++) {
            const float4 wc4 = *(const float4*)(wcp + j * (8 * NSTC));
            const ulonglong2 hA = *(const ulonglong2*)(hup + j * (8 * NSTW));
            const ulonglong2 hB = *(const ulonglong2*)(hrp + j * (8 * NSTW));
            const unsigned long long h2[4] = {hA.x, hA.y, hB.x, hB.y};
            const float wcf[4] = {wc4.x, wc4.y, wc4.z, wc4.w};
            #pragma unroll
            for (int c = 0; c < 4; c++) {
                const unsigned long long dc = dup2(wcf[c]);
                #pragma unroll
                for (int q = 0; q < 4; q++)
                    FFMA2(aC[c * 4 + q], h2[q], dc);
            }
        }

        redstep<8>(aC, b2, 4);
        redstep<4>(aC, b1, 2);
        redstep<2>(aC, b0, 1);

        float pc[4];
        unpack2(pc[0], pc[1], aC[0]); unpack2(pc[2], pc[3], aC[1]);

        #pragma unroll
        for (int i = 0; i < 4; i++) {
            const float cand = tanhf(pc[i] + xc4[i] + bcn);
            cme[i] = fmaf(gu[i], cand - cme[i], cme[i]);
        }

        // broadcast c_new (owned col, 4 rows) to all 4 ranks
        {
            const unsigned long long c01 = pack2(cme[0], cme[1]);
            const unsigned long long c23 = pack2(cme[2], cme[3]);
            #pragma unroll
            for (int d = 0; d < 4; d++) {
                st_cluster_u64(cdst[d], c01);
                st_cluster_u64(cdst[d] + 8, c23);
            }
        }
        __syncthreads();
        if (tid < 4) mbar_arrive_rank(barC, (uint32_t)tid);
        mbar_wait_parity(barC, ph);
    }

    #pragma unroll
    for (int i = 0; i < 4; i++)
        out[(size_t)(m_own + i) * UDIM + col_g] = cme[i];

    CLUSTER_SYNC_();   // no CTA exits while peers' DSMEM stores in flight
}

// =====================================================================
// Launch
// Inputs (metadata order):
//  0:x [256,512,256]  1:a0 [256,256]
//  2:wcx 3:wcc 4:bc   5:wux 6:wuc 7:bu   8:wrx 9:wrc 10:br
// =====================================================================
extern "C" void kernel_launch(void* const* d_in, const int* in_sizes, int n_in,
                              void* d_out, int out_size)
{
    const float* x   = (const float*)d_in[0];
    const float* a0  = (const float*)d_in[1];
    const float* wcx = (const float*)d_in[2];
    const float* wcc = (const float*)d_in[3];
    const float* bc  = (const float*)d_in[4];
    const float* wux = (const float*)d_in[5];
    const float* wuc = (const float*)d_in[6];
    const float* bu  = (const float*)d_in[7];
    const float* wrx = (const float*)d_in[8];
    const float* wrc = (const float*)d_in[9];
    const float* br  = (const float*)d_in[10];
    float* out = (float*)d_out;

    cudaFuncSetAttribute(gru_scan4,
                         cudaFuncAttributeMaxDynamicSharedMemorySize, SMB);

    // Phase 1: x projections (z=0 -> wux, z=1 -> wrx, z=2 -> wcx)
    dim3 g1((MDIM * TDIM) / 128, UDIM / 128, 3);
    xproj_kernel<<<g1, 256>>>(x, wux, wrx, wcx);

    // Phase 2: sequential scan — 32 clusters x 4 CTAs, 128 thr
    gru_scan4<<<128, 128, SMB>>>(wuc, wrc, wcc, bu, br, bc, a0, out);
}

// round 12
// speedup vs baseline: 1.5100x; 1.1738x over previous
#include <cuda_runtime.h>
#include <cuda_bf16.h>
#include <cstdint>

// Problem dims
#define MDIM 256
#define TDIM 512
#define NXDIM 256
#define UDIM 256

// Scratch for x-projections: 3 matrices x [T][M][U] fp32 = 402 MB.
#define XP_STRIDE (33554432ULL) // 512*256*256
__device__ float g_xp[3ULL * XP_STRIDE];

// ---------------- packed f32x2 helpers ----------------
#define FFMA2(c_, a_, b_) \
    asm volatile("fma.rn.f32x2 %0, %1, %2, %0;" : "+l"(c_) : "l"(a_), "l"(b_))
#define ADD2(o_, a_, b_) \
    asm("add.rn.f32x2 %0, %1, %2;" : "=l"(o_) : "l"(a_), "l"(b_))

__device__ __forceinline__ unsigned long long dup2(float a) {
    unsigned long long r;
    asm("mov.b64 %0, {%1, %1};" : "=l"(r) : "f"(a));
    return r;
}
__device__ __forceinline__ unsigned long long pack2(float lo, float hi) {
    unsigned long long r;
    asm("mov.b64 %0, {%1, %2};" : "=l"(r) : "f"(lo), "f"(hi));
    return r;
}
__device__ __forceinline__ void unpack2(float& lo, float& hi, unsigned long long v) {
    asm("mov.b64 {%0, %1}, %2;" : "=f"(lo), "=f"(hi) : "l"(v));
}

// ---------------- cluster / DSMEM helpers ----------------
__device__ __forceinline__ uint32_t smem_u32(const void* p) {
    uint32_t a;
    asm("{ .reg .u64 t; cvta.to.shared.u64 t, %1; cvt.u32.u64 %0, t; }"
        : "=r"(a) : "l"(p));
    return a;
}
__device__ __forceinline__ uint32_t mapa_rank(uint32_t addr, uint32_t rank) {
    uint32_t r;
    asm("mapa.shared::cluster.u32 %0, %1, %2;" : "=r"(r) : "r"(addr), "r"(rank));
    return r;
}
__device__ __forceinline__ void st_cluster_u64(uint32_t addr, unsigned long long v) {
    asm volatile("st.shared::cluster.u64 [%0], %1;" :: "r"(addr), "l"(v) : "memory");
}
__device__ __forceinline__ uint32_t ctarank() {
    uint32_t r; asm("mov.u32 %0, %%cluster_ctarank;" : "=r"(r)); return r;
}
#define CLUSTER_SYNC_() do { \
    asm volatile("barrier.cluster.arrive.aligned;" ::: "memory"); \
    asm volatile("barrier.cluster.wait.aligned;" ::: "memory"); } while (0)

__device__ __forceinline__ void mbar_init(uint32_t bar, uint32_t cnt) {
    asm volatile("mbarrier.init.shared.b64 [%0], %1;" :: "r"(bar), "r"(cnt) : "memory");
}
__device__ __forceinline__ void mbar_arrive_rank(uint32_t local_bar, uint32_t rank) {
    uint32_t remote = mapa_rank(local_bar, rank);
    asm volatile("mbarrier.arrive.release.cluster.shared::cluster.b64 _, [%0];"
                 :: "r"(remote) : "memory");
}
__device__ __forceinline__ void mbar_wait_parity(uint32_t bar, uint32_t parity) {
    uint32_t done;
    asm volatile(
        "{\n\t.reg .pred p;\n\t"
        "mbarrier.try_wait.parity.acquire.cluster.shared::cta.b64 p, [%1], %2;\n\t"
        "selp.b32 %0, 1, 0, p;\n\t}"
        : "=r"(done) : "r"(bar), "r"(parity) : "memory");
    if (!done) {
        asm volatile(
            "{\n\t.reg .pred P1;\n\t"
            "WLOOP_%=:\n\t"
            "mbarrier.try_wait.parity.acquire.cluster.shared::cta.b64 P1, [%0], %1, 0x989680;\n\t"
            "@P1 bra.uni WDONE_%=;\n\t"
            "bra.uni WLOOP_%=;\n\t"
            "WDONE_%=:\n\t}"
            :: "r"(bar), "r"(parity) : "memory");
    }
}

// 64-bit xor shfl (2x SHFL.b32)
__device__ __forceinline__ unsigned long long shfl64(unsigned long long v, int m) {
    return __shfl_xor_sync(0xffffffffu, v, m);
}

// Butterfly reduction step: v[0..2N) -> v[0..N).  sel = this lane keeps
// the upper half.  Partner (lane^m) sends the half this lane keeps.
template<int N>
__device__ __forceinline__ void redstep(unsigned long long* v, bool sel, int m) {
    #pragma unroll
    for (int i = 0; i < N; i++) {
        unsigned long long mine = sel ? v[i + N] : v[i];
        unsigned long long send = sel ? v[i] : v[i + N];
        unsigned long long r = shfl64(send, m);
        ADD2(v[i], mine, r);
    }
}

// =====================================================================
// Phase 1: x projections (unchanged — validated at ~1.06 ms).
// =====================================================================
__global__ __launch_bounds__(256, 1)
void xproj_kernel(const float* __restrict__ x,
                  const float* __restrict__ w_u,
                  const float* __restrict__ w_r,
                  const float* __restrict__ w_c)
{
    const float* __restrict__ w =
        (blockIdx.z == 0) ? w_u : ((blockIdx.z == 1) ? w_r : w_c);
    float* __restrict__ outp = g_xp + (size_t)blockIdx.z * XP_STRIDE;

    const int tid = threadIdx.x;
    const int g0  = blockIdx.x * 128;
    const int t   = g0 >> 8;
    const int m0  = g0 & 255;
    const int n0  = blockIdx.y * 128;

    __shared__ float As[16][132];
    __shared__ float Bs[16][128];

    const int tx = tid & 15;
    const int ty = tid >> 4;

    unsigned long long acc[8][4];
    #pragma unroll
    for (int i = 0; i < 8; i++)
        #pragma unroll
        for (int j = 0; j < 4; j++) acc[i][j] = 0ULL;

    for (int kk = 0; kk < NXDIM; kk += 16) {
        #pragma unroll
        for (int l = 0; l < 2; l++) {
            int f  = tid + l * 256;
            int i  = f >> 2;
            int kv = (f & 3) * 4;
            const float4 v = *(const float4*)(x +
                ((size_t)(m0 + i) * TDIM + t) * NXDIM + kk + kv);
            As[kv + 0][i] = v.x;
            As[kv + 1][i] = v.y;
            As[kv + 2][i] = v.z;
            As[kv + 3][i] = v.w;
        }
        #pragma unroll
        for (int l = 0; l < 2; l++) {
            int f  = tid + l * 256;
            int k  = f >> 5;
            int nn = (f & 31) * 4;
            *(float4*)&Bs[k][nn] =
                *(const float4*)(w + (size_t)(kk + k) * UDIM + n0 + nn);
        }
        __syncthreads();

        #pragma unroll
        for (int k = 0; k < 16; k++) {
            float4 a0v = *(const float4*)&As[k][ty * 8];
            float4 a1v = *(const float4*)&As[k][ty * 8 + 4];
            const unsigned long long* bp =
                (const unsigned long long*)&Bs[k][tx * 8];
            unsigned long long b0 = bp[0], b1 = bp[1], b2 = bp[2], b3 = bp[3];
            float av[8] = {a0v.x, a0v.y, a0v.z, a0v.w,
                           a1v.x, a1v.y, a1v.z, a1v.w};
            #pragma unroll
            for (int i = 0; i < 8; i++) {
                unsigned long long ad = dup2(av[i]);
                FFMA2(acc[i][0], ad, b0);
                FFMA2(acc[i][1], ad, b1);
                FFMA2(acc[i][2], ad, b2);
                FFMA2(acc[i][3], ad, b3);
            }
        }
        __syncthreads();
    }

    #pragma unroll
    for (int i = 0; i < 8; i++) {
        int g = g0 + ty * 8 + i;
        float o[8];
        unpack2(o[0], o[1], acc[i][0]);
        unpack2(o[2], o[3], acc[i][1]);
        unpack2(o[4], o[5], acc[i][2]);
        unpack2(o[6], o[7], acc[i][3]);
        float* op = outp + (size_t)g * UDIM + n0 + tx * 8;
        *(float4*)(op)     = make_float4(o[0], o[1], o[2], o[3]);
        *(float4*)(op + 4) = make_float4(o[4], o[5], o[6], o[7]);
    }
}

// =====================================================================
// Phase 2: GRU scan — 32 clusters x 4 CTAs, 256 threads/CTA.
//   Thread = (ng 0..15 -> cols nbase..nbase+3, ks 0..15 -> k in {ks+16j}).
//   Lane = (ng&1)*16 + ks: ks varies inside every 8-lane LDS phase, so
//   every LDS.128 moves 128 distinct conflict-free bytes (wu/wr stride
//   68: ks*4 mod 32 distinct per phase; wc stride 76: ks*12 mod 32).
//   c rows live in wc row pads (words 64..71 = c[k][row0..7]); h rows
//   0-3 in wu pads, rows 4-7 in wr pads.  Register tile 4 cols x 8 rows
//   x 16 k; 16-way k-reduction via 4-round shfl butterfly; lane ks ends
//   owning (col nbase+(ks>>2), rows 2*(ks&3)..+1) and DSMEM-broadcasts
//   h / c_new (one u64 each) to all 4 ranks.
// =====================================================================
#define NSTW 68
#define NSTC 76
#define OWU 8
#define OWR (OWU + 256 * NSTW)        // 17416
#define OWC (OWR + 256 * NSTW)        // 34824
#define SMF (OWC + 256 * NSTC)        // 54280 floats
#define SMB (SMF * 4)                 // 217120 bytes

__device__ __forceinline__ float sigmoid_f(float z) {
    return 1.0f / (1.0f + __expf(-z));
}

__global__ __launch_bounds__(256, 1) __cluster_dims__(4, 1, 1)
void gru_scan5(const float* __restrict__ wuc,
               const float* __restrict__ wrc,
               const float* __restrict__ wcc,
               const float* __restrict__ bu,
               const float* __restrict__ br,
               const float* __restrict__ bc,
               const float* __restrict__ a0,
               float* __restrict__ out)
{
    extern __shared__ float sm[];
    float* wu_s = sm + OWU;
    float* wr_s = sm + OWR;
    float* wc_s = sm + OWC;

    const int tid = threadIdx.x;
    const uint32_t rank = ctarank();
    const int n0 = (int)rank * 64;
    const int r0 = (blockIdx.x >> 2) * 8;

    const int ks    = tid & 15;
    const int ng    = tid >> 4;
    const int nbase = ng * 4;
    const bool b3 = (ks & 8) != 0, b2 = (ks & 4) != 0,
               b1 = (ks & 2) != 0, b0 = (ks & 1) != 0;
    const int p     = ks & 3;                  // owned row-pair index
    const int col_g = n0 + nbase + (ks >> 2);  // owned unit
    const int m_own = r0 + 2 * p;              // owned rows m_own, m_own+1

    const uint32_t barH = smem_u32(sm);
    const uint32_t barC = barH + 8;
    if (tid == 0) { mbar_init(barH, 4); mbar_init(barC, 4); }

    // ---- weights k-major into smem (each word written once) ----
    for (int i = tid; i < 64 * 256; i += 256) {
        int k = i >> 6, n = i & 63;
        wu_s[k * NSTW + n] = wuc[k * UDIM + n0 + n];
        wr_s[k * NSTW + n] = wrc[k * UDIM + n0 + n];
        wc_s[k * NSTC + n] = wcc[k * UDIM + n0 + n];
    }
    // ---- c init into wc pads: c[u][r] at wc_s[u*76 + 64 + r] ----
    for (int i = tid; i < 256 * 8; i += 256) {
        int u = i >> 3, r = i & 7;
        wc_s[u * NSTC + 64 + r] = a0[(size_t)(r0 + r) * UDIM + u];
    }
    float cme0 = a0[(size_t)(m_own + 0) * UDIM + col_g];
    float cme1 = a0[(size_t)(m_own + 1) * UDIM + col_g];
    const float bun = bu[col_g], brn = br[col_g], bcn = bc[col_g];

    // ---- DSMEM broadcast targets (one u64 per thread per gate) ----
    // h row r lives at wu pad word 64+r (r<4) or wr pad word 64+(r-4).
    uint32_t hbase = (p < 2)
        ? smem_u32(wu_s + col_g * NSTW + 64 + 2 * p)
        : smem_u32(wr_s + col_g * NSTW + 64 + 2 * (p - 2));
    uint32_t cbase = smem_u32(wc_s + col_g * NSTC + 64 + 2 * p);
    uint32_t hdst[4], cdst[4];
    #pragma unroll
    for (int d = 0; d < 4; d++) {
        hdst[d] = mapa_rank(hbase, d);
        cdst[d] = mapa_rank(cbase, d);
    }

    __syncthreads();
    CLUSTER_SYNC_();

    const float* __restrict__ xu = g_xp;
    const float* __restrict__ xr = g_xp + XP_STRIDE;
    const float* __restrict__ xc = g_xp + 2ULL * XP_STRIDE;

    const float* wup = wu_s + ks * NSTW + nbase;
    const float* wrp = wr_s + ks * NSTW + nbase;
    const float* wcp = wc_s + ks * NSTC + nbase;
    const float* cpp = wc_s + ks * NSTC + 64;   // c rows
    const float* hup = wu_s + ks * NSTW + 64;   // h rows 0..3
    const float* hrp = wr_s + ks * NSTW + 64;   // h rows 4..7

    for (int t = 0; t < TDIM; t++) {
        const uint32_t ph = (uint32_t)(t & 1);

        // prefetch x-projection terms for owned (col, 2 rows)
        const size_t xo = (size_t)t * (MDIM * UDIM) + (size_t)m_own * UDIM + col_g;
        const float xu0 = __ldg(xu + xo),        xu1 = __ldg(xu + xo + UDIM);
        const float xr0 = __ldg(xr + xo),        xr1 = __ldg(xr + xo + UDIM);
        const float xc0 = __ldg(xc + xo),        xc1 = __ldg(xc + xo + UDIM);

        // ================= phase A: pre_u, pre_r =================
        unsigned long long aU[16], aR[16];   // [c*4 + q]
        #pragma unroll
        for (int i = 0; i < 16; i++) { aU[i] = 0ULL; aR[i] = 0ULL; }

        #pragma unroll 4
        for (int j = 0; j < 16; j++) {
            const float4 wu4 = *(const float4*)(wup + j * (16 * NSTW));
            const float4 wr4 = *(const float4*)(wrp + j * (16 * NSTW));
            const ulonglong2 cA = *(const ulonglong2*)(cpp + j * (16 * NSTC));
            const ulonglong2 cB = *(const ulonglong2*)(cpp + j * (16 * NSTC) + 4);
            const unsigned long long c2[4] = {cA.x, cA.y, cB.x, cB.y};
            const float wuf[4] = {wu4.x, wu4.y, wu4.z, wu4.w};
            const float wrf[4] = {wr4.x, wr4.y, wr4.z, wr4.w};
            #pragma unroll
            for (int c = 0; c < 4; c++) {
                const unsigned long long du = dup2(wuf[c]);
                const unsigned long long dr = dup2(wrf[c]);
                #pragma unroll
                for (int q = 0; q < 4; q++) {
                    FFMA2(aU[c * 4 + q], c2[q], du);
                    FFMA2(aR[c * 4 + q], c2[q], dr);
                }
            }
        }

        // 16-way k-reduce: cols (b3,b2) then row-pairs (b1,b0)
        redstep<8>(aU, b3, 8);  redstep<8>(aR, b3, 8);
        redstep<4>(aU, b2, 4);  redstep<4>(aR, b2, 4);
        redstep<2>(aU, b1, 2);  redstep<2>(aR, b1, 2);
        redstep<1>(aU, b0, 1);  redstep<1>(aR, b0, 1);

        float pu0, pu1, pr0, pr1;
        unpack2(pu0, pu1, aU[0]);
        unpack2(pr0, pr1, aR[0]);

        const float gu0 = sigmoid_f(pu0 + xu0 + bun);
        const float gu1 = sigmoid_f(pu1 + xu1 + bun);
        const float h0  = sigmoid_f(pr0 + xr0 + brn) * cme0;
        const float h1  = sigmoid_f(pr1 + xr1 + brn) * cme1;

        // broadcast h (owned col, row pair) to all 4 ranks
        {
            const unsigned long long h01 = pack2(h0, h1);
            #pragma unroll
            for (int d = 0; d < 4; d++) st_cluster_u64(hdst[d], h01);
        }
        __syncthreads();
        if (tid < 4) mbar_arrive_rank(barH, (uint32_t)tid);
        mbar_wait_parity(barH, ph);

        // ================= phase B: pre_c =================
        unsigned long long aC[16];
        #pragma unroll
        for (int i = 0; i < 16; i++) aC[i] = 0ULL;

        #pragma unroll 4
        for (int j = 0; j < 16; j++) {
            const float4 wc4 = *(const float4*)(wcp + j * (16 * NSTC));
            const ulonglong2 hA = *(const ulonglong2*)(hup + j * (16 * NSTW));
            const ulonglong2 hB = *(const ulonglong2*)(hrp + j * (16 * NSTW));
            const unsigned long long h2[4] = {hA.x, hA.y, hB.x, hB.y};
            const float wcf[4] = {wc4.x, wc4.y, wc4.z, wc4.w};
            #pragma unroll
            for (int c = 0; c < 4; c++) {
                const unsigned long long dc = dup2(wcf[c]);
                #pragma unroll
                for (int q = 0; q < 4; q++)
                    FFMA2(aC[c * 4 + q], h2[q], dc);
            }
        }

        redstep<8>(aC, b3, 8);
        redstep<4>(aC, b2, 4);
        redstep<2>(aC, b1, 2);
        redstep<1>(aC, b0, 1);

        float pc0, pc1;
        unpack2(pc0, pc1, aC[0]);

        const float cand0 = tanhf(pc0 + xc0 + bcn);
        const float cand1 = tanhf(pc1 + xc1 + bcn);
        cme0 = fmaf(gu0, cand0 - cme0, cme0);
        cme1 = fmaf(gu1, cand1 - cme1, cme1);

        // broadcast c_new (owned col, row pair) to all 4 ranks
        {
            const unsigned long long c01 = pack2(cme0, cme1);
            #pragma unroll
            for (int d = 0; d < 4; d++) st_cluster_u64(cdst[d], c01);
        }
        __syncthreads();
        if (tid < 4) mbar_arrive_rank(barC, (uint32_t)tid);
        mbar_wait_parity(barC, ph);
    }

    out[(size_t)(m_own + 0) * UDIM + col_g] = cme0;
    out[(size_t)(m_own + 1) * UDIM + col_g] = cme1;

    CLUSTER_SYNC_();   // no CTA exits while peers' DSMEM stores in flight
}

// =====================================================================
// Launch
// Inputs (metadata order):
//  0:x [256,512,256]  1:a0 [256,256]
//  2:wcx 3:wcc 4:bc   5:wux 6:wuc 7:bu   8:wrx 9:wrc 10:br
// =====================================================================
extern "C" void kernel_launch(void* const* d_in, const int* in_sizes, int n_in,
                              void* d_out, int out_size)
{
    const float* x   = (const float*)d_in[0];
    const float* a0  = (const float*)d_in[1];
    const float* wcx = (const float*)d_in[2];
    const float* wcc = (const float*)d_in[3];
    const float* bc  = (const float*)d_in[4];
    const float* wux = (const float*)d_in[5];
    const float* wuc = (const float*)d_in[6];
    const float* bu  = (const float*)d_in[7];
    const float* wrx = (const float*)d_in[8];
    const float* wrc = (const float*)d_in[9];
    const float* br  = (const float*)d_in[10];
    float* out = (float*)d_out;

    cudaFuncSetAttribute(gru_scan5,
                         cudaFuncAttributeMaxDynamicSharedMemorySize, SMB);

    // Phase 1: x projections (z=0 -> wux, z=1 -> wrx, z=2 -> wcx)
    dim3 g1((MDIM * TDIM) / 128, UDIM / 128, 3);
    xproj_kernel<<<g1, 256>>>(x, wux, wrx, wcx);

    // Phase 2: sequential scan — 32 clusters x 4 CTAs, 256 thr
    gru_scan5<<<128, 256, SMB>>>(wuc, wrc, wcc, bu, br, bc, a0, out);
}

// round 13
// speedup vs baseline: 1.6055x; 1.0633x over previous
#include <cuda_runtime.h>
#include <cuda_bf16.h>
#include <cstdint>

// Problem dims
#define MDIM 256
#define TDIM 512
#define NXDIM 256
#define UDIM 256

// Scratch for x-projections: 3 matrices x [T][M][U] fp32 = 402 MB.
#define XP_STRIDE (33554432ULL) // 512*256*256
__device__ float g_xp[3ULL * XP_STRIDE];

// ---------------- packed f32x2 helpers ----------------
#define FFMA2(c_, a_, b_) \
    asm volatile("fma.rn.f32x2 %0, %1, %2, %0;" : "+l"(c_) : "l"(a_), "l"(b_))
#define ADD2(o_, a_, b_) \
    asm("add.rn.f32x2 %0, %1, %2;" : "=l"(o_) : "l"(a_), "l"(b_))

__device__ __forceinline__ unsigned long long dup2(float a) {
    unsigned long long r;
    asm("mov.b64 %0, {%1, %1};" : "=l"(r) : "f"(a));
    return r;
}
__device__ __forceinline__ unsigned long long pack2(float lo, float hi) {
    unsigned long long r;
    asm("mov.b64 %0, {%1, %2};" : "=l"(r) : "f"(lo), "f"(hi));
    return r;
}
__device__ __forceinline__ void unpack2(float& lo, float& hi, unsigned long long v) {
    asm("mov.b64 {%0, %1}, %2;" : "=f"(lo), "=f"(hi) : "l"(v));
}

// ---------------- cluster / DSMEM helpers ----------------
__device__ __forceinline__ uint32_t smem_u32(const void* p) {
    uint32_t a;
    asm("{ .reg .u64 t; cvta.to.shared.u64 t, %1; cvt.u32.u64 %0, t; }"
        : "=r"(a) : "l"(p));
    return a;
}
__device__ __forceinline__ uint32_t mapa_rank(uint32_t addr, uint32_t rank) {
    uint32_t r;
    asm("mapa.shared::cluster.u32 %0, %1, %2;" : "=r"(r) : "r"(addr), "r"(rank));
    return r;
}
__device__ __forceinline__ void st_cluster_u64(uint32_t addr, unsigned long long v) {
    asm volatile("st.shared::cluster.u64 [%0], %1;" :: "r"(addr), "l"(v) : "memory");
}
__device__ __forceinline__ uint32_t ctarank() {
    uint32_t r; asm("mov.u32 %0, %%cluster_ctarank;" : "=r"(r)); return r;
}
#define CLUSTER_SYNC_() do { \
    asm volatile("barrier.cluster.arrive.aligned;" ::: "memory"); \
    asm volatile("barrier.cluster.wait.aligned;" ::: "memory"); } while (0)

__device__ __forceinline__ void mbar_init(uint32_t bar, uint32_t cnt) {
    asm volatile("mbarrier.init.shared.b64 [%0], %1;" :: "r"(bar), "r"(cnt) : "memory");
}
__device__ __forceinline__ void mbar_arrive_rank(uint32_t local_bar, uint32_t rank) {
    uint32_t remote = mapa_rank(local_bar, rank);
    asm volatile("mbarrier.arrive.release.cluster.shared::cluster.b64 _, [%0];"
                 :: "r"(remote) : "memory");
}
__device__ __forceinline__ void mbar_wait_parity(uint32_t bar, uint32_t parity) {
    uint32_t done;
    asm volatile(
        "{\n\t.reg .pred p;\n\t"
        "mbarrier.try_wait.parity.acquire.cluster.shared::cta.b64 p, [%1], %2;\n\t"
        "selp.b32 %0, 1, 0, p;\n\t}"
        : "=r"(done) : "r"(bar), "r"(parity) : "memory");
    if (!done) {
        asm volatile(
            "{\n\t.reg .pred P1;\n\t"
            "WLOOP_%=:\n\t"
            "mbarrier.try_wait.parity.acquire.cluster.shared::cta.b64 P1, [%0], %1, 0x989680;\n\t"
            "@P1 bra.uni WDONE_%=;\n\t"
            "bra.uni WLOOP_%=;\n\t"
            "WDONE_%=:\n\t}"
            :: "r"(bar), "r"(parity) : "memory");
    }
}

// 64-bit xor shfl (2x SHFL.b32)
__device__ __forceinline__ unsigned long long shfl64(unsigned long long v, int m) {
    return __shfl_xor_sync(0xffffffffu, v, m);
}

// Butterfly reduction step: v[0..2N) -> v[0..N).
template<int N>
__device__ __forceinline__ void redstep(unsigned long long* v, bool sel, int m) {
    #pragma unroll
    for (int i = 0; i < N; i++) {
        unsigned long long mine = sel ? v[i + N] : v[i];
        unsigned long long send = sel ? v[i] : v[i + N];
        unsigned long long r = shfl64(send, m);
        ADD2(v[i], mine, r);
    }
}

// =====================================================================
// Phase 1: x projections (unchanged — validated at ~1.06 ms).
// =====================================================================
__global__ __launch_bounds__(256, 1)
void xproj_kernel(const float* __restrict__ x,
                  const float* __restrict__ w_u,
                  const float* __restrict__ w_r,
                  const float* __restrict__ w_c)
{
    const float* __restrict__ w =
        (blockIdx.z == 0) ? w_u : ((blockIdx.z == 1) ? w_r : w_c);
    float* __restrict__ outp = g_xp + (size_t)blockIdx.z * XP_STRIDE;

    const int tid = threadIdx.x;
    const int g0  = blockIdx.x * 128;
    const int t   = g0 >> 8;
    const int m0  = g0 & 255;
    const int n0  = blockIdx.y * 128;

    __shared__ float As[16][132];
    __shared__ float Bs[16][128];

    const int tx = tid & 15;
    const int ty = tid >> 4;

    unsigned long long acc[8][4];
    #pragma unroll
    for (int i = 0; i < 8; i++)
        #pragma unroll
        for (int j = 0; j < 4; j++) acc[i][j] = 0ULL;

    for (int kk = 0; kk < NXDIM; kk += 16) {
        #pragma unroll
        for (int l = 0; l < 2; l++) {
            int f  = tid + l * 256;
            int i  = f >> 2;
            int kv = (f & 3) * 4;
            const float4 v = *(const float4*)(x +
                ((size_t)(m0 + i) * TDIM + t) * NXDIM + kk + kv);
            As[kv + 0][i] = v.x;
            As[kv + 1][i] = v.y;
            As[kv + 2][i] = v.z;
            As[kv + 3][i] = v.w;
        }
        #pragma unroll
        for (int l = 0; l < 2; l++) {
            int f  = tid + l * 256;
            int k  = f >> 5;
            int nn = (f & 31) * 4;
            *(float4*)&Bs[k][nn] =
                *(const float4*)(w + (size_t)(kk + k) * UDIM + n0 + nn);
        }
        __syncthreads();

        #pragma unroll
        for (int k = 0; k < 16; k++) {
            float4 a0v = *(const float4*)&As[k][ty * 8];
            float4 a1v = *(const float4*)&As[k][ty * 8 + 4];
            const unsigned long long* bp =
                (const unsigned long long*)&Bs[k][tx * 8];
            unsigned long long b0 = bp[0], b1 = bp[1], b2 = bp[2], b3 = bp[3];
            float av[8] = {a0v.x, a0v.y, a0v.z, a0v.w,
                           a1v.x, a1v.y, a1v.z, a1v.w};
            #pragma unroll
            for (int i = 0; i < 8; i++) {
                unsigned long long ad = dup2(av[i]);
                FFMA2(acc[i][0], ad, b0);
                FFMA2(acc[i][1], ad, b1);
                FFMA2(acc[i][2], ad, b2);
                FFMA2(acc[i][3], ad, b3);
            }
        }
        __syncthreads();
    }

    #pragma unroll
    for (int i = 0; i < 8; i++) {
        int g = g0 + ty * 8 + i;
        float o[8];
        unpack2(o[0], o[1], acc[i][0]);
        unpack2(o[2], o[3], acc[i][1]);
        unpack2(o[4], o[5], acc[i][2]);
        unpack2(o[6], o[7], acc[i][3]);
        float* op = outp + (size_t)g * UDIM + n0 + tx * 8;
        *(float4*)(op)     = make_float4(o[0], o[1], o[2], o[3]);
        *(float4*)(op + 4) = make_float4(o[4], o[5], o[6], o[7]);
    }
}

// =====================================================================
// Phase 2: GRU scan — 32 clusters x 4 CTAs, 256 threads/CTA.
//   Same data layout as R11 (validated).  NEW: latency-hiding k-split —
//   in each GEMV phase, the 4 j-iterations touching the CTA's OWN 64
//   units (j in [4*rank, 4*rank+4)) run first using only CTA-local
//   data (visible after __syncthreads); the cluster mbar_wait happens
//   only before the 12 remote-j iterations, so DSMEM flight + barrier
//   latency overlaps with local FFMA2 work.  The barC wait for step
//   t's c lands inside step t+1's phase A (skipped at t=0).
//   Safety: a peer overwrites our pads only after passing its wait,
//   which needs our arrive, which we post only after all remote reads.
// =====================================================================
#define NSTW 68
#define NSTC 76
#define OWU 8
#define OWR (OWU + 256 * NSTW)        // 17416
#define OWC (OWR + 256 * NSTW)        // 34824
#define SMF (OWC + 256 * NSTC)        // 54280 floats
#define SMB (SMF * 4)                 // 217120 bytes

__device__ __forceinline__ float sigmoid_f(float z) {
    return 1.0f / (1.0f + __expf(-z));
}

__global__ __launch_bounds__(256, 1) __cluster_dims__(4, 1, 1)
void gru_scan6(const float* __restrict__ wuc,
               const float* __restrict__ wrc,
               const float* __restrict__ wcc,
               const float* __restrict__ bu,
               const float* __restrict__ br,
               const float* __restrict__ bc,
               const float* __restrict__ a0,
               float* __restrict__ out)
{
    extern __shared__ float sm[];
    float* wu_s = sm + OWU;
    float* wr_s = sm + OWR;
    float* wc_s = sm + OWC;

    const int tid = threadIdx.x;
    const uint32_t rank = ctarank();
    const int n0 = (int)rank * 64;
    const int r0 = (blockIdx.x >> 2) * 8;

    const int ks    = tid & 15;
    const int ng    = tid >> 4;
    const int nbase = ng * 4;
    const bool b3 = (ks & 8) != 0, b2 = (ks & 4) != 0,
               b1 = (ks & 2) != 0, b0 = (ks & 1) != 0;
    const int p     = ks & 3;                  // owned row-pair index
    const int col_g = n0 + nbase + (ks >> 2);  // owned unit
    const int m_own = r0 + 2 * p;              // owned rows m_own, m_own+1
    const int jloc  = (int)rank * 4;           // local j-block start

    const uint32_t barH = smem_u32(sm);
    const uint32_t barC = barH + 8;
    if (tid == 0) { mbar_init(barH, 4); mbar_init(barC, 4); }

    // ---- weights k-major into smem (each word written once) ----
    for (int i = tid; i < 64 * 256; i += 256) {
        int k = i >> 6, n = i & 63;
        wu_s[k * NSTW + n] = wuc[k * UDIM + n0 + n];
        wr_s[k * NSTW + n] = wrc[k * UDIM + n0 + n];
        wc_s[k * NSTC + n] = wcc[k * UDIM + n0 + n];
    }
    // ---- c init into wc pads: c[u][r] at wc_s[u*76 + 64 + r] ----
    for (int i = tid; i < 256 * 8; i += 256) {
        int u = i >> 3, r = i & 7;
        wc_s[u * NSTC + 64 + r] = a0[(size_t)(r0 + r) * UDIM + u];
    }
    float cme0 = a0[(size_t)(m_own + 0) * UDIM + col_g];
    float cme1 = a0[(size_t)(m_own + 1) * UDIM + col_g];
    const float bun = bu[col_g], brn = br[col_g], bcn = bc[col_g];

    // ---- DSMEM broadcast targets (one u64 per thread per gate) ----
    uint32_t hbase = (p < 2)
        ? smem_u32(wu_s + col_g * NSTW + 64 + 2 * p)
        : smem_u32(wr_s + col_g * NSTW + 64 + 2 * (p - 2));
    uint32_t cbase = smem_u32(wc_s + col_g * NSTC + 64 + 2 * p);
    uint32_t hdst[4], cdst[4];
    #pragma unroll
    for (int d = 0; d < 4; d++) {
        hdst[d] = mapa_rank(hbase, d);
        cdst[d] = mapa_rank(cbase, d);
    }

    __syncthreads();
    CLUSTER_SYNC_();

    const float* __restrict__ xu = g_xp;
    const float* __restrict__ xr = g_xp + XP_STRIDE;
    const float* __restrict__ xc = g_xp + 2ULL * XP_STRIDE;

    const float* wup = wu_s + ks * NSTW + nbase;
    const float* wrp = wr_s + ks * NSTW + nbase;
    const float* wcp = wc_s + ks * NSTC + nbase;
    const float* cpp = wc_s + ks * NSTC + 64;   // c rows
    const float* hup = wu_s + ks * NSTW + 64;   // h rows 0..3
    const float* hrp = wr_s + ks * NSTW + 64;   // h rows 4..7

    unsigned long long aU[16], aR[16], aC[16];

    for (int t = 0; t < TDIM; t++) {
        const uint32_t ph = (uint32_t)(t & 1);

        // prefetch x-projection terms for owned (col, 2 rows)
        const size_t xo = (size_t)t * (MDIM * UDIM) + (size_t)m_own * UDIM + col_g;
        const float xu0 = __ldg(xu + xo), xu1 = __ldg(xu + xo + UDIM);
        const float xr0 = __ldg(xr + xo), xr1 = __ldg(xr + xo + UDIM);
        const float xc0 = __ldg(xc + xo), xc1 = __ldg(xc + xo + UDIM);

        // ================= phase A: pre_u, pre_r =================
        #pragma unroll
        for (int i = 0; i < 16; i++) { aU[i] = 0ULL; aR[i] = 0ULL; }

        auto bodyA = [&](int j) {
            const float4 wu4 = *(const float4*)(wup + j * (16 * NSTW));
            const float4 wr4 = *(const float4*)(wrp + j * (16 * NSTW));
            const ulonglong2 cA = *(const ulonglong2*)(cpp + j * (16 * NSTC));
            const ulonglong2 cB = *(const ulonglong2*)(cpp + j * (16 * NSTC) + 4);
            const unsigned long long c2[4] = {cA.x, cA.y, cB.x, cB.y};
            const float wuf[4] = {wu4.x, wu4.y, wu4.z, wu4.w};
            const float wrf[4] = {wr4.x, wr4.y, wr4.z, wr4.w};
            #pragma unroll
            for (int c = 0; c < 4; c++) {
                const unsigned long long du = dup2(wuf[c]);
                const unsigned long long dr = dup2(wrf[c]);
                #pragma unroll
                for (int q = 0; q < 4; q++) {
                    FFMA2(aU[c * 4 + q], c2[q], du);
                    FFMA2(aR[c * 4 + q], c2[q], dr);
                }
            }
        };

        // local j first (own CTA's c columns — visible since last __syncthreads)
        #pragma unroll
        for (int jj = 0; jj < 4; jj++) bodyA(jloc + jj);
        // wait for remote c of step t-1 (arrived at end of previous step)
        if (t > 0) mbar_wait_parity(barC, (uint32_t)((t - 1) & 1));
        // remote j blocks
        #pragma unroll
        for (int g = 1; g < 4; g++) {
            const int jb = (((int)rank + g) & 3) * 4;
            #pragma unroll
            for (int jj = 0; jj < 4; jj++) bodyA(jb + jj);
        }

        // 16-way k-reduce: cols (b3,b2) then row-pairs (b1,b0)
        redstep<8>(aU, b3, 8);  redstep<8>(aR, b3, 8);
        redstep<4>(aU, b2, 4);  redstep<4>(aR, b2, 4);
        redstep<2>(aU, b1, 2);  redstep<2>(aR, b1, 2);
        redstep<1>(aU, b0, 1);  redstep<1>(aR, b0, 1);

        float pu0, pu1, pr0, pr1;
        unpack2(pu0, pu1, aU[0]);
        unpack2(pr0, pr1, aR[0]);

        const float h0  = sigmoid_f(pr0 + xr0 + brn) * cme0;
        const float h1  = sigmoid_f(pr1 + xr1 + brn) * cme1;
        // broadcast h immediately (gu computes under the store flight)
        {
            const unsigned long long h01 = pack2(h0, h1);
            #pragma unroll
            for (int d = 0; d < 4; d++) st_cluster_u64(hdst[d], h01);
        }
        const float gu0 = sigmoid_f(pu0 + xu0 + bun);
        const float gu1 = sigmoid_f(pu1 + xu1 + bun);

        __syncthreads();                       // local h visible CTA-wide
        if (tid < 4) mbar_arrive_rank(barH, (uint32_t)tid);

        // ================= phase B: pre_c =================
        #pragma unroll
        for (int i = 0; i < 16; i++) aC[i] = 0ULL;

        auto bodyB = [&](int j) {
            const float4 wc4 = *(const float4*)(wcp + j * (16 * NSTC));
            const ulonglong2 hA = *(const ulonglong2*)(hup + j * (16 * NSTW));
            const ulonglong2 hB = *(const ulonglong2*)(hrp + j * (16 * NSTW));
            const unsigned long long h2[4] = {hA.x, hA.y, hB.x, hB.y};
            const float wcf[4] = {wc4.x, wc4.y, wc4.z, wc4.w};
            #pragma unroll
            for (int c = 0; c < 4; c++) {
                const unsigned long long dc = dup2(wcf[c]);
                #pragma unroll
                for (int q = 0; q < 4; q++)
                    FFMA2(aC[c * 4 + q], h2[q], dc);
            }
        };

        // local j first (own CTA's h columns)
        #pragma unroll
        for (int jj = 0; jj < 4; jj++) bodyB(jloc + jj);
        // wait for remote h of this step
        mbar_wait_parity(barH, ph);
        // remote j blocks
        #pragma unroll
        for (int g = 1; g < 4; g++) {
            const int jb = (((int)rank + g) & 3) * 4;
            #pragma unroll
            for (int jj = 0; jj < 4; jj++) bodyB(jb + jj);
        }

        redstep<8>(aC, b3, 8);
        redstep<4>(aC, b2, 4);
        redstep<2>(aC, b1, 2);
        redstep<1>(aC, b0, 1);

        float pc0, pc1;
        unpack2(pc0, pc1, aC[0]);

        const float cand0 = tanhf(pc0 + xc0 + bcn);
        const float cand1 = tanhf(pc1 + xc1 + bcn);
        cme0 = fmaf(gu0, cand0 - cme0, cme0);
        cme1 = fmaf(gu1, cand1 - cme1, cme1);

        // broadcast c_new; arrive barC (wait happens in next step's phase A)
        {
            const unsigned long long c01 = pack2(cme0, cme1);
            #pragma unroll
            for (int d = 0; d < 4; d++) st_cluster_u64(cdst[d], c01);
        }
        __syncthreads();                       // local c visible CTA-wide
        if (tid < 4) mbar_arrive_rank(barC, (uint32_t)tid);
    }

    out[(size_t)(m_own + 0) * UDIM + col_g] = cme0;
    out[(size_t)(m_own + 1) * UDIM + col_g] = cme1;

    CLUSTER_SYNC_();   // no CTA exits while peers' DSMEM stores in flight
}

// =====================================================================
// Launch
// Inputs (metadata order):
//  0:x [256,512,256]  1:a0 [256,256]
//  2:wcx 3:wcc 4:bc   5:wux 6:wuc 7:bu   8:wrx 9:wrc 10:br
// =====================================================================
extern "C" void kernel_launch(void* const* d_in, const int* in_sizes, int n_in,
                              void* d_out, int out_size)
{
    const float* x   = (const float*)d_in[0];
    const float* a0  = (const float*)d_in[1];
    const float* wcx = (const float*)d_in[2];
    const float* wcc = (const float*)d_in[3];
    const float* bc  = (const float*)d_in[4];
    const float* wux = (const float*)d_in[5];
    const float* wuc = (const float*)d_in[6];
    const float* bu  = (const float*)d_in[7];
    const float* wrx = (const float*)d_in[8];
    const float* wrc = (const float*)d_in[9];
    const float* br  = (const float*)d_in[10];
    float* out = (float*)d_out;

    cudaFuncSetAttribute(gru_scan6,
                         cudaFuncAttributeMaxDynamicSharedMemorySize, SMB);

    // Phase 1: x projections (z=0 -> wux, z=1 -> wrx, z=2 -> wcx)
    dim3 g1((MDIM * TDIM) / 128, UDIM / 128, 3);
    xproj_kernel<<<g1, 256>>>(x, wux, wrx, wcx);

    // Phase 2: sequential scan — 32 clusters x 4 CTAs, 256 thr
    gru_scan6<<<128, 256, SMB>>>(wuc, wrc, wcc, bu, br, bc, a0, out);
}